// round 8
// baseline (speedup 1.0000x reference)
#include <cuda_runtime.h>

#define D        256
#define H        16
#define RTILE    256    // rows per block
#define THREADS  256
#define CHUNK    8      // k-columns staged per chunk
#define NCH      32     // 256/8
#define STAGES   3
#define XCSTRIDE 2048   // floats per stage buffer (256*8)

typedef unsigned long long u64;

static __device__ __forceinline__ u64 pack2(float a, float b) {
    u64 r; asm("mov.b64 %0, {%1, %2};" : "=l"(r) : "f"(a), "f"(b)); return r;
}
static __device__ __forceinline__ void unpack2(u64 v, float& a, float& b) {
    asm("mov.b64 {%0, %1}, %2;" : "=f"(a), "=f"(b) : "l"(v));
}
static __device__ __forceinline__ u64 fma2(u64 a, u64 b, u64 c) {
    u64 d; asm("fma.rn.f32x2 %0, %1, %2, %3;" : "=l"(d) : "l"(a), "l"(b), "l"(c)); return d;
}
static __device__ __forceinline__ float ex2f(float x) {
    float r; asm("ex2.approx.f32 %0, %1;" : "=f"(r) : "f"(x)); return r;
}
static __device__ __forceinline__ float rcpf(float x) {
    float r; asm("rcp.approx.f32 %0, %1;" : "=f"(r) : "f"(x)); return r;
}
static __device__ __forceinline__ float sigmoid2(float s) {
    return rcpf(1.0f + ex2f(s * -2.8853900817779268f));
}
static __device__ __forceinline__ void cpa16(float* dst, const float* src) {
    unsigned s = (unsigned)__cvta_generic_to_shared(dst);
    asm volatile("cp.async.ca.shared.global [%0], [%1], 16;" :: "r"(s), "l"(src) : "memory");
}
static __device__ __forceinline__ void cpa_commit() {
    asm volatile("cp.async.commit_group;" ::: "memory");
}

// Shared (floats): W1s [0,4096) | xc [4096, 4096+3*2048) 3-stage chunk bufs
//                  hb  [10240, 14336) h [256][16] quad-XOR swizzle
__global__ __launch_bounds__(THREADS, 4)
void fb_kernel(const float* __restrict__ x, const float* __restrict__ W1,
               const float* __restrict__ W2, float* __restrict__ out, int n)
{
    extern __shared__ float smem[];
    float* W1s = smem;
    float* xc  = smem + 4096;
    float* hb  = smem + 4096 + STAGES * XCSTRIDE;

    const int t     = threadIdx.x;
    const int row0  = blockIdx.x * RTILE;
    const int nrows = min(RTILE, n - row0);

    // stage W1 (plain STS; covered by first loop barrier)
    #pragma unroll
    for (int i = 0; i < 16; i++) W1s[t + i * THREADS] = W1[t + i * THREADS];

    // staging helper data: thread covers slots t and t+256
    const int rrA = t >> 1,          qA = t & 1;
    const int rrB = (t + 256) >> 1,  qB = t & 1;   // (t+256)&1 == t&1
    const int sA  = qA ^ ((rrA >> 2) & 1);
    const int sB  = qB ^ ((rrB >> 2) & 1);
    const long long gA = (long long)(row0 + rrA) * D + 4 * qA;
    const long long gB = (long long)(row0 + rrB) * D + 4 * qB;
    const bool okA = rrA < nrows, okB = rrB < nrows;

    // prologue: prefetch chunks 0 and 1
    #pragma unroll
    for (int c = 0; c < 2; c++) {
        float* buf = xc + c * XCSTRIDE;
        if (okA) cpa16(buf + rrA * CHUNK + 4 * sA, x + gA + c * CHUNK);
        if (okB) cpa16(buf + rrB * CHUNK + 4 * sB, x + gB + c * CHUNK);
        cpa_commit();
    }

    // ================= pass 1: h = relu(x @ W1), pipelined ==================
    const int r  = t;
    const int sw = (r >> 2) & 1;                  // my row's slot swizzle bit
    const int w0 = 4 * (0 ^ sw) * H;              // W row offset for memory slot 0
    const int w1 = 4 * (1 ^ sw) * H;              // W row offset for memory slot 1
    u64 acc[8];
    #pragma unroll
    for (int i = 0; i < 8; i++) acc[i] = 0ULL;

    int stage = 0, pstage = 2;
    for (int c = 0; c < NCH; c++) {
        if (c + 1 < NCH) asm volatile("cp.async.wait_group 1;" ::: "memory");
        else             asm volatile("cp.async.wait_group 0;" ::: "memory");
        __syncthreads();

        if (c + 2 < NCH) {
            float* buf = xc + pstage * XCSTRIDE;
            if (okA) cpa16(buf + rrA * CHUNK + 4 * sA, x + gA + (c + 2) * CHUNK);
            if (okB) cpa16(buf + rrB * CHUNK + 4 * sB, x + gB + (c + 2) * CHUNK);
            cpa_commit();
            pstage = (pstage == 2) ? 0 : pstage + 1;
        }

        const float* myrow = xc + stage * XCSTRIDE + r * CHUNK;
        const float* wbase = W1s + c * CHUNK * H;
        #pragma unroll
        for (int m = 0; m < 2; m++) {
            float4 xv = *reinterpret_cast<const float4*>(myrow + 4 * m);
            const float* wr = wbase + (m ? w1 : w0);
            #pragma unroll
            for (int i = 0; i < 4; i++) {
                float xs = (i == 0) ? xv.x : (i == 1) ? xv.y : (i == 2) ? xv.z : xv.w;
                u64 xx = pack2(xs, xs);
                const ulonglong2* wq = reinterpret_cast<const ulonglong2*>(wr + i * H);
                ulonglong2 wa = wq[0], wb = wq[1];
                acc[0] = fma2(xx, wa.x, acc[0]);
                acc[1] = fma2(xx, wa.y, acc[1]);
                acc[2] = fma2(xx, wb.x, acc[2]);
                acc[3] = fma2(xx, wb.y, acc[3]);
                ulonglong2 wc = wq[2], wd = wq[3];
                acc[4] = fma2(xx, wc.x, acc[4]);
                acc[5] = fma2(xx, wc.y, acc[5]);
                acc[6] = fma2(xx, wd.x, acc[6]);
                acc[7] = fma2(xx, wd.y, acc[7]);
            }
        }
        stage = (stage == 2) ? 0 : stage + 1;
    }

    // ReLU + store h row (STS.128, quad-XOR swizzle -> conflict-free)
    {
        const int qs = (r >> 1) & 3;
        #pragma unroll
        for (int q = 0; q < 4; q++) {
            float a0, a1, b0, b1;
            unpack2(acc[2 * q + 0], a0, a1);
            unpack2(acc[2 * q + 1], b0, b1);
            float4 v = make_float4(fmaxf(a0, 0.f), fmaxf(a1, 0.f),
                                   fmaxf(b0, 0.f), fmaxf(b1, 0.f));
            *reinterpret_cast<float4*>(hb + r * H + 4 * (q ^ qs)) = v;
        }
    }
    __syncthreads();

    // ================= pass 2: lane = k-column; W2 in registers =============
    const int w = t >> 5, lane = t & 31;
    const int rbase = (w >> 2) * 128;
    const int kq = w & 3;
    const int k0 = kq * 64 + lane;
    const int k1 = k0 + 32;

    u64 w2a[8], w2b[8];
    #pragma unroll
    for (int j = 0; j < 8; j++) {
        w2a[j] = pack2(W2[(2 * j) * D + k0], W2[(2 * j + 1) * D + k0]);
        w2b[j] = pack2(W2[(2 * j) * D + k1], W2[(2 * j + 1) * D + k1]);
    }

    const int rend = max(0, min(128, nrows - rbase));
    const long long gbase = (long long)(row0 + rbase) * D;

    float nx0 = 0.f, nx1 = 0.f;
    if (rend > 0) { nx0 = x[gbase + k0]; nx1 = x[gbase + k1]; }

    #pragma unroll 2
    for (int ri = 0; ri < rend; ri++) {
        float xv0 = nx0, xv1 = nx1;
        if (ri + 1 < rend) {
            nx0 = x[gbase + (long long)(ri + 1) * D + k0];
            nx1 = x[gbase + (long long)(ri + 1) * D + k1];
        }
        int rr = rbase + ri;
        int fq = (rr >> 1) & 3;
        const float* hr = hb + rr * H;

        u64 sa = 0ULL, sb = 0ULL;
        #pragma unroll
        for (int q = 0; q < 4; q++) {
            ulonglong2 hq = *reinterpret_cast<const ulonglong2*>(hr + 4 * (q ^ fq));
            sa = fma2(hq.x, w2a[2 * q + 0], sa);
            sb = fma2(hq.x, w2b[2 * q + 0], sb);
            sa = fma2(hq.y, w2a[2 * q + 1], sa);
            sb = fma2(hq.y, w2b[2 * q + 1], sb);
        }
        float a0, a1, b0, b1;
        unpack2(sa, a0, a1);
        float s0 = a0 + a1;
        unpack2(sb, b0, b1);
        float s1 = b0 + b1;

        long long g = gbase + (long long)ri * D;
        out[g + k0] = xv0 * sigmoid2(s0);
        out[g + k1] = xv1 * sigmoid2(s1);
    }
}

extern "C" void kernel_launch(void* const* d_in, const int* in_sizes, int n_in,
                              void* d_out, int out_size) {
    const float* x  = (const float*)d_in[0];
    const float* W1 = (const float*)d_in[1];
    const float* W2 = (const float*)d_in[2];
    float* out = (float*)d_out;
    int n = in_sizes[0] / D;

    int smem_bytes = (4096 + STAGES * XCSTRIDE + 4096) * (int)sizeof(float); // 56 KB
    cudaFuncSetAttribute(fb_kernel, cudaFuncAttributeMaxDynamicSharedMemorySize, smem_bytes);
    int grid = (n + RTILE - 1) / RTILE;
    fb_kernel<<<grid, THREADS, smem_bytes>>>(x, W1, W2, out, n);
}

// round 9
// speedup vs baseline: 1.3090x; 1.3090x over previous
#include <cuda_runtime.h>

#define D        256
#define H        16
#define RTILE    128    // rows per block (= threads)
#define THREADS  128
#define CHUNK    16     // k-columns staged per chunk
#define NCH      16     // 256/16
#define XCFL     (RTILE * CHUNK)   // floats per stage buffer (2048)

typedef unsigned long long u64;

static __device__ __forceinline__ u64 pack2(float a, float b) {
    u64 r; asm("mov.b64 %0, {%1, %2};" : "=l"(r) : "f"(a), "f"(b)); return r;
}
static __device__ __forceinline__ void unpack2(u64 v, float& a, float& b) {
    asm("mov.b64 {%0, %1}, %2;" : "=f"(a), "=f"(b) : "l"(v));
}
static __device__ __forceinline__ u64 fma2(u64 a, u64 b, u64 c) {
    u64 d; asm("fma.rn.f32x2 %0, %1, %2, %3;" : "=l"(d) : "l"(a), "l"(b), "l"(c)); return d;
}
static __device__ __forceinline__ float ex2f(float x) {
    float r; asm("ex2.approx.f32 %0, %1;" : "=f"(r) : "f"(x)); return r;
}
static __device__ __forceinline__ float rcpf(float x) {
    float r; asm("rcp.approx.f32 %0, %1;" : "=f"(r) : "f"(x)); return r;
}
static __device__ __forceinline__ float sigmoid2(float s) {
    return rcpf(1.0f + ex2f(s * -2.8853900817779268f));
}
static __device__ __forceinline__ void cpa16(float* dst, const float* src) {
    unsigned s = (unsigned)__cvta_generic_to_shared(dst);
    asm volatile("cp.async.ca.shared.global [%0], [%1], 16;" :: "r"(s), "l"(src) : "memory");
}
static __device__ __forceinline__ void cpa_commit() {
    asm volatile("cp.async.commit_group;" ::: "memory");
}

// Shared (floats): W1s [0,4096) | xcA [4096,6144) | xcB [6144,8192)
// hb (pass 2) reuses xcA: [128][16] quad-XOR swizzle. Total 32 KB.
__global__ __launch_bounds__(THREADS, 6)
void fb_kernel(const float* __restrict__ x, const float* __restrict__ W1,
               const float* __restrict__ W2, float* __restrict__ out, int n)
{
    extern __shared__ float smem[];
    float* W1s = smem;
    float* xcA = smem + 4096;
    float* xcB = smem + 4096 + XCFL;
    float* hb  = xcA;                      // union: valid after pass 1

    const int t     = threadIdx.x;
    const int row0  = blockIdx.x * RTILE;
    const int nrows = min(RTILE, n - row0);

    // stage W1 (covered by first loop barrier)
    #pragma unroll
    for (int i = 0; i < 32; i++) W1s[t + i * THREADS] = W1[t + i * THREADS];

    // staging map: thread covers float4-slots t + it*128, it=0..3
    // slot idx -> row rr = idx>>2, quad q = idx&3, swizzled slot q ^ ((rr>>1)&3)
    // prologue: prefetch chunks 0 (A) and 1 (B)
    #pragma unroll
    for (int c = 0; c < 2; c++) {
        float* buf = c ? xcB : xcA;
        #pragma unroll
        for (int it = 0; it < 4; it++) {
            int idx = t + it * THREADS;
            int rr = idx >> 2, q = idx & 3;
            if (rr < nrows)
                cpa16(buf + rr * CHUNK + 4 * (q ^ ((rr >> 1) & 3)),
                      x + (long long)(row0 + rr) * D + c * CHUNK + 4 * q);
        }
        cpa_commit();
    }

    // ================= pass 1: h = relu(x @ W1), 1 row/thread ===============
    const int r   = t;
    const int qs1 = (r >> 1) & 3;
    u64 acc[8];
    #pragma unroll
    for (int i = 0; i < 8; i++) acc[i] = 0ULL;

    for (int c = 0; c < NCH; c++) {
        if (c < NCH - 1) asm volatile("cp.async.wait_group 1;" ::: "memory");
        else             asm volatile("cp.async.wait_group 0;" ::: "memory");
        __syncthreads();

        const float* myrow = (c & 1 ? xcB : xcA) + r * CHUNK;
        const float* wbase = W1s + c * CHUNK * H;
        #pragma unroll
        for (int q = 0; q < 4; q++) {
            float4 xv = *reinterpret_cast<const float4*>(myrow + 4 * (q ^ qs1));
            #pragma unroll
            for (int i = 0; i < 4; i++) {
                float xs = (i == 0) ? xv.x : (i == 1) ? xv.y : (i == 2) ? xv.z : xv.w;
                u64 xx = pack2(xs, xs);
                const ulonglong2* wq =
                    reinterpret_cast<const ulonglong2*>(wbase + (4 * q + i) * H);
                ulonglong2 wa = wq[0], wb = wq[1];
                acc[0] = fma2(xx, wa.x, acc[0]);
                acc[1] = fma2(xx, wa.y, acc[1]);
                acc[2] = fma2(xx, wb.x, acc[2]);
                acc[3] = fma2(xx, wb.y, acc[3]);
                ulonglong2 wc = wq[2], wd = wq[3];
                acc[4] = fma2(xx, wc.x, acc[4]);
                acc[5] = fma2(xx, wc.y, acc[5]);
                acc[6] = fma2(xx, wd.x, acc[6]);
                acc[7] = fma2(xx, wd.y, acc[7]);
            }
        }
        __syncthreads();                    // all readers done with buf(c&1)

        if (c + 2 < NCH) {                  // prefetch c+2 into the freed buffer
            float* buf = (c & 1) ? xcB : xcA;
            #pragma unroll
            for (int it = 0; it < 4; it++) {
                int idx = t + it * THREADS;
                int rr = idx >> 2, q = idx & 3;
                if (rr < nrows)
                    cpa16(buf + rr * CHUNK + 4 * (q ^ ((rr >> 1) & 3)),
                          x + (long long)(row0 + rr) * D + (c + 2) * CHUNK + 4 * q);
            }
            cpa_commit();
        }
    }

    // ReLU + store h row into hb (=xcA), quad-XOR swizzle -> conflict-free
    #pragma unroll
    for (int q = 0; q < 4; q++) {
        float a0, a1, b0, b1;
        unpack2(acc[2 * q + 0], a0, a1);
        unpack2(acc[2 * q + 1], b0, b1);
        float4 v = make_float4(fmaxf(a0, 0.f), fmaxf(a1, 0.f),
                               fmaxf(b0, 0.f), fmaxf(b1, 0.f));
        *reinterpret_cast<float4*>(hb + r * H + 4 * (q ^ qs1)) = v;
    }
    __syncthreads();

    // ================= pass 2: lane = k-column; W2 in registers =============
    // 4 warps, each covers 2 k-columns (k0, k0+32) for all 128 rows.
    const int w = t >> 5, lane = t & 31;
    const int k0 = w * 64 + lane;
    const int k1 = k0 + 32;

    u64 w2a[8], w2b[8];
    #pragma unroll
    for (int j = 0; j < 8; j++) {
        w2a[j] = pack2(W2[(2 * j) * D + k0], W2[(2 * j + 1) * D + k0]);
        w2b[j] = pack2(W2[(2 * j) * D + k1], W2[(2 * j + 1) * D + k1]);
    }

    const long long gbase = (long long)row0 * D;
    float nx0 = 0.f, nx1 = 0.f;
    if (nrows > 0) { nx0 = x[gbase + k0]; nx1 = x[gbase + k1]; }

    #pragma unroll 2
    for (int rr = 0; rr < nrows; rr++) {
        float xv0 = nx0, xv1 = nx1;
        if (rr + 1 < nrows) {
            nx0 = x[gbase + (long long)(rr + 1) * D + k0];
            nx1 = x[gbase + (long long)(rr + 1) * D + k1];
        }
        int fq = (rr >> 1) & 3;
        const float* hr = hb + rr * H;

        u64 sa = 0ULL, sb = 0ULL;
        #pragma unroll
        for (int q = 0; q < 4; q++) {
            ulonglong2 hq = *reinterpret_cast<const ulonglong2*>(hr + 4 * (q ^ fq));
            sa = fma2(hq.x, w2a[2 * q + 0], sa);
            sb = fma2(hq.x, w2b[2 * q + 0], sb);
            sa = fma2(hq.y, w2a[2 * q + 1], sa);
            sb = fma2(hq.y, w2b[2 * q + 1], sb);
        }
        float a0, a1, b0, b1;
        unpack2(sa, a0, a1);
        float s0 = a0 + a1;
        unpack2(sb, b0, b1);
        float s1 = b0 + b1;

        long long g = gbase + (long long)rr * D;
        out[g + k0] = xv0 * sigmoid2(s0);
        out[g + k1] = xv1 * sigmoid2(s1);
    }
}

extern "C" void kernel_launch(void* const* d_in, const int* in_sizes, int n_in,
                              void* d_out, int out_size) {
    const float* x  = (const float*)d_in[0];
    const float* W1 = (const float*)d_in[1];
    const float* W2 = (const float*)d_in[2];
    float* out = (float*)d_out;
    int n = in_sizes[0] / D;

    int smem_bytes = (4096 + 2 * XCFL) * (int)sizeof(float);   // 32 KB -> 6 CTAs/SM
    cudaFuncSetAttribute(fb_kernel, cudaFuncAttributeMaxDynamicSharedMemorySize, smem_bytes);
    int grid = (n + RTILE - 1) / RTILE;
    fb_kernel<<<grid, THREADS, smem_bytes>>>(x, W1, W2, out, n);
}

// round 11
// speedup vs baseline: 1.4054x; 1.0736x over previous
#include <cuda_runtime.h>

#define D        256
#define H        16
#define RTILE    256    // rows per block (= threads)
#define THREADS  256
#define CHUNK    16     // k-columns staged per chunk
#define NCH      16     // 256/16
#define XCFL     (RTILE * CHUNK)   // floats per stage buffer (4096)

typedef unsigned long long u64;

static __device__ __forceinline__ u64 pack2(float a, float b) {
    u64 r; asm("mov.b64 %0, {%1, %2};" : "=l"(r) : "f"(a), "f"(b)); return r;
}
static __device__ __forceinline__ void unpack2(u64 v, float& a, float& b) {
    asm("mov.b64 {%0, %1}, %2;" : "=f"(a), "=f"(b) : "l"(v));
}
static __device__ __forceinline__ u64 fma2(u64 a, u64 b, u64 c) {
    u64 d; asm("fma.rn.f32x2 %0, %1, %2, %3;" : "=l"(d) : "l"(a), "l"(b), "l"(c)); return d;
}
static __device__ __forceinline__ float ex2f(float x) {
    float r; asm("ex2.approx.f32 %0, %1;" : "=f"(r) : "f"(x)); return r;
}
static __device__ __forceinline__ float rcpf(float x) {
    float r; asm("rcp.approx.f32 %0, %1;" : "=f"(r) : "f"(x)); return r;
}
static __device__ __forceinline__ float sigmoid2(float s) {
    return rcpf(1.0f + ex2f(s * -2.8853900817779268f));
}
static __device__ __forceinline__ void cpa16(float* dst, const float* src) {
    unsigned s = (unsigned)__cvta_generic_to_shared(dst);
    asm volatile("cp.async.ca.shared.global [%0], [%1], 16;" :: "r"(s), "l"(src) : "memory");
}
static __device__ __forceinline__ void cpa_commit() {
    asm volatile("cp.async.commit_group;" ::: "memory");
}

// Shared (floats): W1s [0,4096) | xcA [4096,8192) | xcB [8192,12288)
// hb (pass 2) reuses xcA: [256][16] quad-XOR swizzle. Total 48 KB -> 4 CTAs/SM.
__global__ __launch_bounds__(THREADS, 4)
void fb_kernel(const float* __restrict__ x, const float* __restrict__ W1,
               const float* __restrict__ W2, float* __restrict__ out, int n)
{
    extern __shared__ float smem[];
    float* W1s = smem;
    float* xcA = smem + 4096;
    float* xcB = smem + 8192;
    float* hb  = xcA;                      // union: valid after pass 1

    const int t     = threadIdx.x;
    const int row0  = blockIdx.x * RTILE;
    const int nrows = min(RTILE, n - row0);

    // stage W1 (covered by first chunk's barrier)
    #pragma unroll
    for (int i = 0; i < 16; i++) W1s[t + i * THREADS] = W1[t + i * THREADS];

    // prologue: prefetch chunks 0 (A) and 1 (B)
    #pragma unroll
    for (int c = 0; c < 2; c++) {
        float* buf = c ? xcB : xcA;
        #pragma unroll
        for (int it = 0; it < 4; it++) {
            int idx = t + it * THREADS;    // 0..1023 float4 slots
            int rr = idx >> 2, q = idx & 3;
            if (rr < nrows)
                cpa16(buf + rr * CHUNK + 4 * (q ^ ((rr >> 1) & 3)),
                      x + (long long)(row0 + rr) * D + c * CHUNK + 4 * q);
        }
        cpa_commit();
    }

    // ================= pass 1: h = relu(x @ W1), 1 row/thread ===============
    const int r   = t;
    const int qs1 = (r >> 1) & 3;
    u64 acc[8];
    #pragma unroll
    for (int i = 0; i < 8; i++) acc[i] = 0ULL;

    for (int c = 0; c < NCH; c++) {
        if (c < NCH - 1) asm volatile("cp.async.wait_group 1;" ::: "memory");
        else             asm volatile("cp.async.wait_group 0;" ::: "memory");
        __syncthreads();

        const float* myrow = (c & 1 ? xcB : xcA) + r * CHUNK;
        const float* wbase = W1s + c * CHUNK * H;
        #pragma unroll
        for (int q = 0; q < 4; q++) {
            float4 xv = *reinterpret_cast<const float4*>(myrow + 4 * (q ^ qs1));
            #pragma unroll
            for (int i = 0; i < 4; i++) {
                float xs = (i == 0) ? xv.x : (i == 1) ? xv.y : (i == 2) ? xv.z : xv.w;
                u64 xx = pack2(xs, xs);
                const ulonglong2* wq =
                    reinterpret_cast<const ulonglong2*>(wbase + (4 * q + i) * H);
                ulonglong2 wa = wq[0], wb = wq[1];
                acc[0] = fma2(xx, wa.x, acc[0]);
                acc[1] = fma2(xx, wa.y, acc[1]);
                acc[2] = fma2(xx, wb.x, acc[2]);
                acc[3] = fma2(xx, wb.y, acc[3]);
                ulonglong2 wc = wq[2], wd = wq[3];
                acc[4] = fma2(xx, wc.x, acc[4]);
                acc[5] = fma2(xx, wc.y, acc[5]);
                acc[6] = fma2(xx, wd.x, acc[6]);
                acc[7] = fma2(xx, wd.y, acc[7]);
            }
        }
        __syncthreads();                    // everyone done reading buf(c&1)

        if (c + 2 < NCH) {                  // prefetch c+2 into the freed buffer
            float* buf = (c & 1) ? xcB : xcA;
            #pragma unroll
            for (int it = 0; it < 4; it++) {
                int idx = t + it * THREADS;
                int rr = idx >> 2, q = idx & 3;
                if (rr < nrows)
                    cpa16(buf + rr * CHUNK + 4 * (q ^ ((rr >> 1) & 3)),
                          x + (long long)(row0 + rr) * D + (c + 2) * CHUNK + 4 * q);
            }
            cpa_commit();
        }
    }

    // ReLU + store h row into hb (=xcA), quad-XOR swizzle -> conflict-free
    #pragma unroll
    for (int q = 0; q < 4; q++) {
        float a0, a1, b0, b1;
        unpack2(acc[2 * q + 0], a0, a1);
        unpack2(acc[2 * q + 1], b0, b1);
        float4 v = make_float4(fmaxf(a0, 0.f), fmaxf(a1, 0.f),
                               fmaxf(b0, 0.f), fmaxf(b1, 0.f));
        *reinterpret_cast<float4*>(hb + r * H + 4 * (q ^ qs1)) = v;
    }
    __syncthreads();

    // ================= pass 2: lane = k-column; W2 in registers =============
    const int w = t >> 5, lane = t & 31;
    const int rbase = (w >> 2) * 128;      // warps 0-3: rows 0-127; 4-7: 128-255
    const int kq = w & 3;
    const int k0 = kq * 64 + lane;
    const int k1 = k0 + 32;

    u64 w2a[8], w2b[8];
    #pragma unroll
    for (int j = 0; j < 8; j++) {
        w2a[j] = pack2(W2[(2 * j) * D + k0], W2[(2 * j + 1) * D + k0]);
        w2b[j] = pack2(W2[(2 * j) * D + k1], W2[(2 * j + 1) * D + k1]);
    }

    const int rend = max(0, min(128, nrows - rbase));
    const long long gbase = (long long)(row0 + rbase) * D;

    float nx0 = 0.f, nx1 = 0.f;
    if (rend > 0) { nx0 = x[gbase + k0]; nx1 = x[gbase + k1]; }

    #pragma unroll 4
    for (int ri = 0; ri < rend; ri++) {
        float xv0 = nx0, xv1 = nx1;
        if (ri + 1 < rend) {
            nx0 = x[gbase + (long long)(ri + 1) * D + k0];
            nx1 = x[gbase + (long long)(ri + 1) * D + k1];
        }
        int rr = rbase + ri;
        int fq = (rr >> 1) & 3;
        const float* hr = hb + rr * H;

        u64 sa = 0ULL, sb = 0ULL;
        #pragma unroll
        for (int q = 0; q < 4; q++) {
            ulonglong2 hq = *reinterpret_cast<const ulonglong2*>(hr + 4 * (q ^ fq));
            sa = fma2(hq.x, w2a[2 * q + 0], sa);
            sb = fma2(hq.x, w2b[2 * q + 0], sb);
            sa = fma2(hq.y, w2a[2 * q + 1], sa);
            sb = fma2(hq.y, w2b[2 * q + 1], sb);
        }
        float a0, a1, b0, b1;
        unpack2(sa, a0, a1);
        float s0 = a0 + a1;
        unpack2(sb, b0, b1);
        float s1 = b0 + b1;

        long long g = gbase + (long long)ri * D;
        out[g + k0] = xv0 * sigmoid2(s0);
        out[g + k1] = xv1 * sigmoid2(s1);
    }
}

extern "C" void kernel_launch(void* const* d_in, const int* in_sizes, int n_in,
                              void* d_out, int out_size) {
    const float* x  = (const float*)d_in[0];
    const float* W1 = (const float*)d_in[1];
    const float* W2 = (const float*)d_in[2];
    float* out = (float*)d_out;
    int n = in_sizes[0] / D;

    int smem_bytes = (4096 + 2 * XCFL) * (int)sizeof(float);   // 48 KB -> 4 CTAs/SM
    cudaFuncSetAttribute(fb_kernel, cudaFuncAttributeMaxDynamicSharedMemorySize, smem_bytes);
    int grid = (n + RTILE - 1) / RTILE;
    fb_kernel<<<grid, THREADS, smem_bytes>>>(x, W1, W2, out, n);
}